// round 1
// baseline (speedup 1.0000x reference)
#include <cuda_runtime.h>
#include <cstdint>

// PositionDropout: out[b,s,d] = scale[b,s] * x[b,s,d]
//   prox[b,s]  : piecewise-linear proximity weight, clipped to [0,1]
//   mask[b,s]  : jax.random.bernoulli(key(42), prox)  (Threefry-2x32, partitionable)
//   scale[b,s] = mask / (prox + 1e-5)
//
// Two kernels:
//   1) scale_kernel: 32768 threads, one Threefry eval each -> g_scale[B*S]
//   2) apply_kernel: one block per (b,s) row, 192 threads, float4 streaming

#define B_  64
#define S_  512
#define D_  768
#define NROWS (B_ * S_)        // 32768
#define V4_PER_ROW (D_ / 4)    // 192

__device__ float g_scale[NROWS];

// Threefry-2x32, 20 rounds, key (0, 42). ks2 = k1 ^ k2 ^ 0x1BD11BDA.
__device__ __forceinline__ void threefry2x32_0_42(uint32_t c0, uint32_t c1,
                                                  uint32_t& o0, uint32_t& o1) {
    const uint32_t ks0 = 0u;
    const uint32_t ks1 = 42u;
    const uint32_t ks2 = 0x1BD11BDAu ^ 0u ^ 42u;
    uint32_t x0 = c0 + ks0;
    uint32_t x1 = c1 + ks1;
#define TF_R(r) { x0 += x1; x1 = __funnelshift_l(x1, x1, (r)); x1 ^= x0; }
    TF_R(13) TF_R(15) TF_R(26) TF_R(6)   x0 += ks1; x1 += ks2 + 1u;
    TF_R(17) TF_R(29) TF_R(16) TF_R(24)  x0 += ks2; x1 += ks0 + 2u;
    TF_R(13) TF_R(15) TF_R(26) TF_R(6)   x0 += ks0; x1 += ks1 + 3u;
    TF_R(17) TF_R(29) TF_R(16) TF_R(24)  x0 += ks1; x1 += ks2 + 4u;
    TF_R(13) TF_R(15) TF_R(26) TF_R(6)   x0 += ks2; x1 += ks0 + 5u;
#undef TF_R
    o0 = x0; o1 = x1;
}

__global__ void scale_kernel(const int* __restrict__ abi,   // [B,2]
                             const int* __restrict__ tl,    // [B]
                             const int* __restrict__ al) {  // [B]
    unsigned i = blockIdx.x * blockDim.x + threadIdx.x;
    if (i >= NROWS) return;

    // Partitionable threefry random bits: 64-bit linear index split into
    // (hi, lo) u32 counters -> threefry2x32 -> bits = out0 ^ out1.
    uint32_t r0, r1;
    threefry2x32_0_42(0u, i, r0, r1);
    uint32_t bits = r0 ^ r1;

    // uniform in [0,1): bitcast((bits >> 9) | 0x3f800000) - 1.0f
    float u = __uint_as_float((bits >> 9) | 0x3F800000u) - 1.0f;

    int b = i >> 9;            // i / S_
    int s = i & (S_ - 1);

    int b0i = abi[2 * b];
    int b1i = abi[2 * b + 1];
    int tli = tl[b];
    int ctxi = tli - al[b];

    float jf  = (float)s;
    float b0f = (float)b0i;
    float b1f = (float)b1i;
    float ctx = (float)ctxi;

    float prox;
    if (jf < b0f)        prox = 1.0f - __fdiv_rn(b0f - jf, ctx);
    else if (jf <= b1f)  prox = __fdiv_rn(1.0f, ctx);
    else                 prox = 1.0f - __fdiv_rn(jf - b1f, ctx);
    if (!(jf < (float)tli)) prox = 0.0f;
    prox = fminf(fmaxf(prox, 0.0f), 1.0f);

    float mask = (u < prox) ? 1.0f : 0.0f;
    g_scale[i] = __fdiv_rn(mask, prox + 1e-5f);
}

__global__ void apply_kernel(const float4* __restrict__ x,
                             float4* __restrict__ out) {
    unsigned row = blockIdx.x;                       // 0 .. NROWS-1
    unsigned idx = row * V4_PER_ROW + threadIdx.x;   // float4 index
    float sc = g_scale[row];                         // broadcast load
    float4 v = x[idx];
    v.x *= sc; v.y *= sc; v.z *= sc; v.w *= sc;
    out[idx] = v;
}

extern "C" void kernel_launch(void* const* d_in, const int* in_sizes, int n_in,
                              void* d_out, int out_size) {
    const float* x   = (const float*)d_in[0];
    const int*   abi = (const int*)d_in[1];
    const int*   tl  = (const int*)d_in[2];
    const int*   al  = (const int*)d_in[3];
    float* out = (float*)d_out;

    scale_kernel<<<NROWS / 256, 256>>>(abi, tl, al);
    apply_kernel<<<NROWS, V4_PER_ROW>>>((const float4*)x, (float4*)out);
}

// round 2
// speedup vs baseline: 1.0638x; 1.0638x over previous
#include <cuda_runtime.h>
#include <cstdint>

// PositionDropout fused: out[b,s,d] = scale[b,s] * x[b,s,d]
// One kernel. Each block owns 4 consecutive (b,s) rows:
//   - threads 0..3 compute scale[row] (Threefry-2x32 bernoulli + prox) -> smem
//   - all 192 threads stream 4 rows with front-batched float4 loads (MLP=4)

#define B_  64
#define S_  512
#define D_  768
#define NROWS (B_ * S_)        // 32768
#define V4_PER_ROW (D_ / 4)    // 192
#define RPB 4                  // rows per block
#define NBLK (NROWS / RPB)     // 8192

// Threefry-2x32, 20 rounds, key (0, 42). ks2 = k1 ^ k2 ^ 0x1BD11BDA.
__device__ __forceinline__ uint32_t threefry_bits_0_42(uint32_t i) {
    const uint32_t ks0 = 0u;
    const uint32_t ks1 = 42u;
    const uint32_t ks2 = 0x1BD11BDAu ^ 0u ^ 42u;
    uint32_t x0 = 0u + ks0;    // counter hi = 0
    uint32_t x1 = i + ks1;     // counter lo = linear index
#define TF_R(r) { x0 += x1; x1 = __funnelshift_l(x1, x1, (r)); x1 ^= x0; }
    TF_R(13) TF_R(15) TF_R(26) TF_R(6)   x0 += ks1; x1 += ks2 + 1u;
    TF_R(17) TF_R(29) TF_R(16) TF_R(24)  x0 += ks2; x1 += ks0 + 2u;
    TF_R(13) TF_R(15) TF_R(26) TF_R(6)   x0 += ks0; x1 += ks1 + 3u;
    TF_R(17) TF_R(29) TF_R(16) TF_R(24)  x0 += ks1; x1 += ks2 + 4u;
    TF_R(13) TF_R(15) TF_R(26) TF_R(6)   x0 += ks2; x1 += ks0 + 5u;
#undef TF_R
    return x0 ^ x1;
}

__global__ void __launch_bounds__(V4_PER_ROW) pd_fused_kernel(
        const float4* __restrict__ x,
        float4* __restrict__ out,
        const int* __restrict__ abi,   // [B,2]
        const int* __restrict__ tl,    // [B]
        const int* __restrict__ al) {  // [B]
    __shared__ float s_sc[RPB];

    unsigned row0 = blockIdx.x * RPB;
    unsigned t = threadIdx.x;

    if (t < RPB) {
        unsigned i = row0 + t;                 // linear [B,S] index
        uint32_t bits = threefry_bits_0_42(i);
        // uniform in [0,1): bitcast((bits>>9) | 0x3f800000) - 1.0f
        float u = __uint_as_float((bits >> 9) | 0x3F800000u) - 1.0f;

        int b = i >> 9;                        // i / S_
        int s = i & (S_ - 1);

        int b0i = abi[2 * b];
        int b1i = abi[2 * b + 1];
        int tli = tl[b];
        int ctxi = tli - al[b];

        float jf  = (float)s;
        float b0f = (float)b0i;
        float b1f = (float)b1i;
        float ctx = (float)ctxi;

        float prox;
        if (jf < b0f)        prox = 1.0f - __fdiv_rn(b0f - jf, ctx);
        else if (jf <= b1f)  prox = __fdiv_rn(1.0f, ctx);
        else                 prox = 1.0f - __fdiv_rn(jf - b1f, ctx);
        if (!(jf < (float)tli)) prox = 0.0f;
        prox = fminf(fmaxf(prox, 0.0f), 1.0f);

        float mask = (u < prox) ? 1.0f : 0.0f;
        s_sc[t] = __fdiv_rn(mask, prox + 1e-5f);
    }
    __syncthreads();

    // Stream 4 rows, front-batched loads for MLP=4.
    const float4* xp = x + (size_t)row0 * V4_PER_ROW + t;
    float4 v0 = xp[0 * V4_PER_ROW];
    float4 v1 = xp[1 * V4_PER_ROW];
    float4 v2 = xp[2 * V4_PER_ROW];
    float4 v3 = xp[3 * V4_PER_ROW];

    float s0 = s_sc[0], s1 = s_sc[1], s2 = s_sc[2], s3 = s_sc[3];

    v0.x *= s0; v0.y *= s0; v0.z *= s0; v0.w *= s0;
    v1.x *= s1; v1.y *= s1; v1.z *= s1; v1.w *= s1;
    v2.x *= s2; v2.y *= s2; v2.z *= s2; v2.w *= s2;
    v3.x *= s3; v3.y *= s3; v3.z *= s3; v3.w *= s3;

    float4* op = out + (size_t)row0 * V4_PER_ROW + t;
    op[0 * V4_PER_ROW] = v0;
    op[1 * V4_PER_ROW] = v1;
    op[2 * V4_PER_ROW] = v2;
    op[3 * V4_PER_ROW] = v3;
}

extern "C" void kernel_launch(void* const* d_in, const int* in_sizes, int n_in,
                              void* d_out, int out_size) {
    const float* x   = (const float*)d_in[0];
    const int*   abi = (const int*)d_in[1];
    const int*   tl  = (const int*)d_in[2];
    const int*   al  = (const int*)d_in[3];
    float* out = (float*)d_out;

    pd_fused_kernel<<<NBLK, V4_PER_ROW>>>((const float4*)x, (float4*)out,
                                          abi, tl, al);
}